// round 13
// baseline (speedup 1.0000x reference)
#include <cuda_runtime.h>
#include <cuda_bf16.h>
#include <cstdint>

#define NB  4
#define NC  512
#define NN  4096
#define NCQ 64

// ---------------- device scratch ----------------
__device__ float g_Wr[640 * NC];                     // rounded unified [wq;wk;wv]
__device__ float g_Q[NB * NN * NCQ];                 // [b][n][k] tf32-rounded
__device__ float g_K[NB * NN * NCQ];                 // [b][m][k] tf32-rounded
__device__ __nv_bfloat16 g_Vh[(size_t)NB * NN * NC]; // [b][m][c] bf16
__device__ __nv_bfloat16 g_P[(size_t)NB * NN * NN];  // [b][q][m] bf16, 134 MB
__device__ float g_L[NB * NN];                       // 1 / sum(exp(s-20))

__device__ __forceinline__ float f2tff(float v) {
    uint32_t t;
    asm("cvt.rna.tf32.f32 %0, %1;" : "=r"(t) : "f"(v));
    return __uint_as_float(t);
}
__device__ __forceinline__ uint32_t f2tffu(float v) {
    uint32_t t;
    asm("cvt.rna.tf32.f32 %0, %1;" : "=r"(t) : "f"(v));
    return t;
}

__device__ __forceinline__ void mma8(float c[4],
                                     uint32_t a0, uint32_t a1, uint32_t a2, uint32_t a3,
                                     uint32_t b0, uint32_t b1) {
    asm volatile(
        "mma.sync.aligned.m16n8k8.row.col.f32.tf32.tf32.f32 "
        "{%0,%1,%2,%3},{%4,%5,%6,%7},{%8,%9},{%0,%1,%2,%3};"
        : "+f"(c[0]), "+f"(c[1]), "+f"(c[2]), "+f"(c[3])
        : "r"(a0), "r"(a1), "r"(a2), "r"(a3), "r"(b0), "r"(b1));
}

__device__ __forceinline__ void mma16(float c[4], const uint32_t a[4],
                                      uint32_t b0, uint32_t b1) {
    asm volatile(
        "mma.sync.aligned.m16n8k16.row.col.f32.bf16.bf16.f32 "
        "{%0,%1,%2,%3},{%4,%5,%6,%7},{%8,%9},{%0,%1,%2,%3};"
        : "+f"(c[0]), "+f"(c[1]), "+f"(c[2]), "+f"(c[3])
        : "r"(a[0]), "r"(a[1]), "r"(a[2]), "r"(a[3]), "r"(b0), "r"(b1));
}

__device__ __forceinline__ void ldsm4(uint32_t r[4], uint32_t addr) {
    asm volatile("ldmatrix.sync.aligned.m8n8.x4.shared.b16 {%0,%1,%2,%3},[%4];"
                 : "=r"(r[0]), "=r"(r[1]), "=r"(r[2]), "=r"(r[3]) : "r"(addr));
}
__device__ __forceinline__ void ldsm4t(uint32_t r[4], uint32_t addr) {
    asm volatile("ldmatrix.sync.aligned.m8n8.x4.trans.shared.b16 {%0,%1,%2,%3},[%4];"
                 : "=r"(r[0]), "=r"(r[1]), "=r"(r[2]), "=r"(r[3]) : "r"(addr));
}
__device__ __forceinline__ void cpa16(uint32_t s, const void* g) {
    asm volatile("cp.async.cg.shared.global [%0],[%1],16;" :: "r"(s), "l"(g));
}

// =========================================================================
// Kernel 0: pre-round W (once) into unified g_Wr[o][c], o in [0,640).
// =========================================================================
__global__ __launch_bounds__(256) void pam_roundw(
    const float* __restrict__ wq, const float* __restrict__ wk,
    const float* __restrict__ wv)
{
    int i = blockIdx.x * 256 + threadIdx.x;      // float4 index, 81920 total
    int p = i * 4;
    int o = p >> 9, c = p & 511;
    const float* src = (o < 64) ? (wq + (size_t)o * NC + c)
                     : (o < 128) ? (wk + (size_t)(o - 64) * NC + c)
                                 : (wv + (size_t)(o - 128) * NC + c);
    float4 v = *reinterpret_cast<const float4*>(src);
    v.x = f2tff(v.x); v.y = f2tff(v.y); v.z = f2tff(v.z); v.w = f2tff(v.w);
    *reinterpret_cast<float4*>(g_Wr + p) = v;
}

// =========================================================================
// Kernel 1: fused QKV projection (round-11 passing version, unchanged).
// =========================================================================
#define PJ_WS    33792
#define SMEM_PJ  70656

__global__ __launch_bounds__(256) void pam_proj(
    const float* __restrict__ x,
    const float* __restrict__ bq, const float* __restrict__ bk,
    const float* __restrict__ bv)
{
    extern __shared__ char sm[];
    uint32_t sb = (uint32_t)__cvta_generic_to_shared(sm);
    const uint32_t AsA = sb, WsA = sb + PJ_WS;

    const int b  = blockIdx.z;
    const int n0 = blockIdx.x * 128;
    const int oc = blockIdx.y * 128;
    const int t    = threadIdx.x;
    const int lane = t & 31;
    const int wid  = t >> 5;
    const int mg = wid & 3, og = wid >> 2;
    const int m0 = mg * 32, o0 = og * 64;
    const int r0 = lane >> 2, c2 = lane & 3;

    const int wr  = ((lane >> 4) & 1) * 8 + (lane & 7);
    const int wk2 = ((lane >> 3) & 1) * 4;

    {
#pragma unroll
        for (int r = 0; r < 4; r++) {
            int idx = t + 256 * r;
            int kk = idx >> 5, j4 = idx & 31;
            cpa16(AsA + kk * 528 + j4 * 16,
                  x + ((size_t)(b * NC + kk)) * NN + n0 + j4 * 4);
        }
#pragma unroll
        for (int r = 0; r < 4; r++) {
            int idx = t + 256 * r;
            int row = idx >> 3, f4 = idx & 7;
            cpa16(WsA + row * 144 + f4 * 16,
                  g_Wr + (size_t)(oc + row) * NC + f4 * 4);
        }
        asm volatile("cp.async.commit_group;" ::: "memory");
    }

    float acc[2][8][4];
#pragma unroll
    for (int mf = 0; mf < 2; mf++)
#pragma unroll
        for (int nf = 0; nf < 8; nf++)
#pragma unroll
            for (int e = 0; e < 4; e++) acc[mf][nf][e] = 0.f;

    for (int it = 0; it < 16; it++) {
        const int buf = it & 1;
        if (it < 15) {
            const int nb = (it + 1) & 1, kc = (it + 1) * 32;
#pragma unroll
            for (int r = 0; r < 4; r++) {
                int idx = t + 256 * r;
                int kk = idx >> 5, j4 = idx & 31;
                cpa16(AsA + nb * 16896 + kk * 528 + j4 * 16,
                      x + ((size_t)(b * NC + kc + kk)) * NN + n0 + j4 * 4);
            }
#pragma unroll
            for (int r = 0; r < 4; r++) {
                int idx = t + 256 * r;
                int row = idx >> 3, f4 = idx & 7;
                cpa16(WsA + nb * 18432 + row * 144 + f4 * 16,
                      g_Wr + (size_t)(oc + row) * NC + kc + f4 * 4);
            }
            asm volatile("cp.async.commit_group;" ::: "memory");
            asm volatile("cp.async.wait_group 1;" ::: "memory");
        } else {
            asm volatile("cp.async.wait_group 0;" ::: "memory");
        }
        __syncthreads();

        const float* AsB = (const float*)(sm + buf * 16896);
        const uint32_t WsB = WsA + buf * 18432;

#pragma unroll
        for (int kq = 0; kq < 32; kq += 8) {
            uint32_t a[2][4];
#pragma unroll
            for (int mf = 0; mf < 2; mf++) {
                const float* Ab = AsB + (kq + c2) * 132 + m0 + mf * 16 + r0;
                a[mf][0] = f2tffu(Ab[0]);
                a[mf][1] = f2tffu(Ab[8]);
                a[mf][2] = f2tffu(Ab[4 * 132]);
                a[mf][3] = f2tffu(Ab[4 * 132 + 8]);
            }
#pragma unroll
            for (int i = 0; i < 4; i++) {
                uint32_t wf[4];
                ldsm4(wf, WsB + (uint32_t)(o0 + i * 16 + wr) * 144 + (kq + wk2) * 4);
                mma8(acc[0][2 * i],     a[0][0], a[0][1], a[0][2], a[0][3], wf[0], wf[1]);
                mma8(acc[0][2 * i + 1], a[0][0], a[0][1], a[0][2], a[0][3], wf[2], wf[3]);
                mma8(acc[1][2 * i],     a[1][0], a[1][1], a[1][2], a[1][3], wf[0], wf[1]);
                mma8(acc[1][2 * i + 1], a[1][0], a[1][1], a[1][2], a[1][3], wf[2], wf[3]);
            }
        }
        __syncthreads();
    }

    const int c0 = 2 * (lane & 3);
#pragma unroll
    for (int mf = 0; mf < 2; mf++) {
#pragma unroll
        for (int nf = 0; nf < 8; nf++) {
#pragma unroll
            for (int e = 0; e < 4; e++) {
                int row = m0 + mf * 16 + r0 + ((e >= 2) ? 8 : 0);
                int col = o0 + (nf >> 1) * 16 + (nf & 1) * 8 + c0 + (e & 1);
                int o = oc + col;
                int n = n0 + row;
                if (o < 64) {
                    g_Q[((size_t)b * NN + n) * NCQ + o] = f2tff(acc[mf][nf][e] + bq[o]);
                } else if (o < 128) {
                    g_K[((size_t)b * NN + n) * NCQ + (o - 64)] = f2tff(acc[mf][nf][e] + bk[o - 64]);
                } else {
                    g_Vh[((size_t)b * NN + n) * NC + (o - 128)] =
                        __float2bfloat16(acc[mf][nf][e] + bv[o - 128]);
                }
            }
        }
    }
}

// =========================================================================
// Kernel 2: S = Q K^T once, P = exp(S-20) -> global bf16 via smem staging,
// Linv -> global. Grid 32 x 4 = 128 CTAs (round-11 passing version).
// =========================================================================
#define SP_KS    34816
#define SP_LP    69632
#define SP_PST   71680
#define SMEM_SP  90112

__global__ __launch_bounds__(512, 1) void pam_sp()
{
    extern __shared__ char sm[];
    float* Lpart = (float*)(sm + SP_LP);
    __nv_bfloat16* Pst = (__nv_bfloat16*)(sm + SP_PST);
    uint32_t sb = (uint32_t)__cvta_generic_to_shared(sm);
    const uint32_t QsA = sb, KsA = sb + SP_KS;

    const int b  = blockIdx.y;
    const int n0 = blockIdx.x * 128;
    const int t = threadIdx.x, lane = t & 31, wid = t >> 5;
    const int qs = wid >> 2, mg = wid & 3;
    const int qb = qs * 32;
    const int r0 = lane >> 2, c2 = lane & 3;

    const int qrow = (lane & 7) + (((lane >> 3) & 1) << 3);
    const int qkof = ((lane >> 4) & 1) * 4;
    const int krow = (lane & 7) + (((lane >> 4) & 1) << 3);
    const int kkof = ((lane >> 3) & 1) * 4;

    {
        const float* gq = g_Q + ((size_t)b * NN + n0) * NCQ;
#pragma unroll
        for (int r2 = 0; r2 < 4; r2++) {
            int cid = t + 512 * r2; int row = cid >> 4, c16 = cid & 15;
            cpa16(QsA + row * 272 + c16 * 16, gq + row * 64 + c16 * 4);
        }
        const float* gk = g_K + ((size_t)b * NN) * NCQ;
#pragma unroll
        for (int r2 = 0; r2 < 2; r2++) {
            int cid = t + 512 * r2; int row = cid >> 4, c16 = cid & 15;
            cpa16(KsA + row * 272 + c16 * 16, gk + row * 64 + c16 * 4);
        }
        asm volatile("cp.async.commit_group;" ::: "memory");
    }

    float Lacc[4] = {0.f, 0.f, 0.f, 0.f};
    __nv_bfloat16* gp = g_P + ((size_t)b * NN + n0) * NN;

    for (int mt = 0; mt < 64; mt++) {
        const int buf = mt & 1;
        if (mt < 63) {
            const int nb = (mt + 1) & 1;
            const float* gk = g_K + ((size_t)b * NN + (mt + 1) * 64) * NCQ;
#pragma unroll
            for (int r2 = 0; r2 < 2; r2++) {
                int cid = t + 512 * r2; int row = cid >> 4, c16 = cid & 15;
                cpa16(KsA + nb * 17408 + row * 272 + c16 * 16, gk + row * 64 + c16 * 4);
            }
            asm volatile("cp.async.commit_group;" ::: "memory");
            asm volatile("cp.async.wait_group 1;" ::: "memory");
        } else {
            asm volatile("cp.async.wait_group 0;" ::: "memory");
        }
        __syncthreads();

        const uint32_t KbA = KsA + buf * 17408;
        float sacc[2][2][4];
#pragma unroll
        for (int mf = 0; mf < 2; mf++)
#pragma unroll
            for (int nf = 0; nf < 2; nf++)
#pragma unroll
                for (int e = 0; e < 4; e++) sacc[mf][nf][e] = 0.f;

#pragma unroll
        for (int j = 0; j < 8; j++) {
            uint32_t kf[4];
            ldsm4(kf, KbA + (uint32_t)(mg * 16 + krow) * 272 + (j * 8 + kkof) * 4);
#pragma unroll
            for (int mf = 0; mf < 2; mf++) {
                uint32_t qf[4];
                ldsm4(qf, QsA + (uint32_t)(qb + mf * 16 + qrow) * 272 + (j * 8 + qkof) * 4);
                mma8(sacc[mf][0], qf[0], qf[1], qf[2], qf[3], kf[0], kf[1]);
                mma8(sacc[mf][1], qf[0], qf[1], qf[2], qf[3], kf[2], kf[3]);
            }
        }

#pragma unroll
        for (int mf = 0; mf < 2; mf++)
#pragma unroll
            for (int nf = 0; nf < 2; nf++)
#pragma unroll
                for (int h = 0; h < 2; h++) {
                    float e0 = __expf(sacc[mf][nf][2 * h]     - 20.f);
                    float e1 = __expf(sacc[mf][nf][2 * h + 1] - 20.f);
                    Lacc[mf * 2 + h] += e0 + e1;
                    uint32_t pk;
                    asm("cvt.rn.bf16x2.f32 %0, %1, %2;" : "=r"(pk) : "f"(e1), "f"(e0));
                    int q = qb + mf * 16 + h * 8 + r0;
                    int m = mg * 16 + nf * 8 + 2 * c2;
                    *(uint32_t*)((char*)Pst + q * 144 + m * 2) = pk;
                }
        __syncthreads();

#pragma unroll
        for (int r2 = 0; r2 < 2; r2++) {
            int idx = t + 512 * r2;
            int row = idx >> 3, ch = idx & 7;
            *(float4*)(gp + (size_t)row * NN + mt * 64 + ch * 8) =
                *(const float4*)((const char*)Pst + row * 144 + ch * 16);
        }
    }

#pragma unroll
    for (int i = 0; i < 4; i++) {
        float v = Lacc[i];
        v += __shfl_xor_sync(0xffffffffu, v, 1);
        v += __shfl_xor_sync(0xffffffffu, v, 2);
        if (c2 == 0) Lpart[mg * 128 + qb + (i >> 1) * 16 + (i & 1) * 8 + r0] = v;
    }
    __syncthreads();
    if (t < 128)
        g_L[(size_t)b * NN + n0 + t] =
            1.f / (Lpart[t] + Lpart[128 + t] + Lpart[256 + t] + Lpart[384 + t]);
}

// =========================================================================
// Kernel 3: O = P @ V + epilogue. P A-fragments loaded DIRECTLY FROM GLOBAL
// (one aligned LDG.32 per fragment register — row-major P matches the
// m16n8k16 A layout exactly). No P smem staging at all.
// V: 3-stage cp.async pipeline, 1 sync/tile (round-11 structure).
// Grid 32 x 1 x 4 = 128 CTAs = one wave, persistent over 2 channel halves.
// Smem: Vs bf16[3][64][264] | Linv f32[128]  (Ostage overlays Vs in epilogue)
// =========================================================================
#define PV_LI    101376
#define SMEM_PV  101888

__global__ __launch_bounds__(512, 1) void pam_pv(
    const float* __restrict__ x,
    const float* __restrict__ gamma,
    float* __restrict__ out)
{
    extern __shared__ char sm[];
    float* Linv   = (float*)(sm + PV_LI);
    float* Ostage = (float*)sm;
    uint32_t sb = (uint32_t)__cvta_generic_to_shared(sm);
    const uint32_t VsA = sb;

    const int b   = blockIdx.z;
    const int n0  = blockIdx.x * 128;
    const int t = threadIdx.x, lane = t & 31, wid = t >> 5;
    const int qs = wid >> 2, cg = wid & 3;
    const int qb = qs * 32;
    const int r0 = lane >> 2, c2 = lane & 3;

    const __nv_bfloat16* __restrict__ gp = g_P + ((size_t)b * NN + n0) * NN;

    if (t < 128) Linv[t] = g_L[(size_t)b * NN + n0 + t];

    const int ly = (lane >> 4) * 8;
    const int lx = lane & 15;
    const float gv2 = gamma[0];

    // global row pointers for this thread's A-fragment rows (loop-invariant)
    const __nv_bfloat16* __restrict__ pA0 = gp + (size_t)(qb + r0) * NN + 2 * c2;
    const __nv_bfloat16* __restrict__ pA1 = pA0 + (size_t)8 * NN;
    const __nv_bfloat16* __restrict__ pA2 = pA0 + (size_t)16 * NN;
    const __nv_bfloat16* __restrict__ pA3 = pA0 + (size_t)24 * NN;

    for (int p2 = 0; p2 < 2; p2++) {
        const int ch0 = p2 * 256;
        const __nv_bfloat16* gv = g_Vh + ((size_t)b * NN) * NC + ch0;

        // prologue: V tiles 0 and 1, one commit group each
#pragma unroll
        for (int pre = 0; pre < 2; pre++) {
            const int m1 = pre * 64;
#pragma unroll
            for (int r2 = 0; r2 < 4; r2++) {
                int cid = t + 512 * r2; int row = cid >> 5, c16 = cid & 31;
                cpa16(VsA + pre * 33792 + row * 528 + c16 * 16,
                      gv + (size_t)(m1 + row) * NC + c16 * 8);
            }
            asm volatile("cp.async.commit_group;" ::: "memory");
        }

        float oacc[2][8][4];
#pragma unroll
        for (int mf = 0; mf < 2; mf++)
#pragma unroll
            for (int nf = 0; nf < 8; nf++)
#pragma unroll
                for (int e = 0; e < 4; e++) oacc[mf][nf][e] = 0.f;

        for (int mt = 0; mt < 64; mt++) {
            if (mt < 63) {
                asm volatile("cp.async.wait_group 1;" ::: "memory");
            } else {
                asm volatile("cp.async.wait_group 0;" ::: "memory");
            }
            __syncthreads();

            // prefetch V tile mt+2 into slot (mt+2)%3 (safe: all warps past sync)
            if (mt < 62) {
                const int sl = (mt + 2) % 3, m1 = (mt + 2) * 64;
#pragma unroll
                for (int r2 = 0; r2 < 4; r2++) {
                    int cid = t + 512 * r2; int row = cid >> 5, c16 = cid & 31;
                    cpa16(VsA + sl * 33792 + row * 528 + c16 * 16,
                          gv + (size_t)(m1 + row) * NC + c16 * 8);
                }
                asm volatile("cp.async.commit_group;" ::: "memory");
            }

            const uint32_t Vb = VsA + (mt % 3) * 33792;
            const int mcol = mt * 64;
#pragma unroll
            for (int ks = 0; ks < 4; ks++) {
                const int k0 = mcol + ks * 16;
                uint32_t a[2][4];
                // A-fragments straight from global (bits identical to ldsm path)
                a[0][0] = __ldg((const uint32_t*)(pA0 + k0));
                a[0][1] = __ldg((const uint32_t*)(pA1 + k0));
                a[0][2] = __ldg((const uint32_t*)(pA0 + k0 + 8));
                a[0][3] = __ldg((const uint32_t*)(pA1 + k0 + 8));
                a[1][0] = __ldg((const uint32_t*)(pA2 + k0));
                a[1][1] = __ldg((const uint32_t*)(pA3 + k0));
                a[1][2] = __ldg((const uint32_t*)(pA2 + k0 + 8));
                a[1][3] = __ldg((const uint32_t*)(pA3 + k0 + 8));
#pragma unroll
                for (int cb = 0; cb < 4; cb++) {
                    uint32_t bb[4];
                    ldsm4t(bb, Vb + (uint32_t)(ks * 16 + lx) * 528 + (cg * 64 + cb * 16 + ly) * 2);
                    mma16(oacc[0][cb * 2],     a[0], bb[0], bb[1]);
                    mma16(oacc[0][cb * 2 + 1], a[0], bb[2], bb[3]);
                    mma16(oacc[1][cb * 2],     a[1], bb[0], bb[1]);
                    mma16(oacc[1][cb * 2 + 1], a[1], bb[2], bb[3]);
                }
            }
        }
        __syncthreads();   // all reads of Vs done before Ostage overlays it

        // epilogue: two 128-channel passes through Ostage, coalesced writes
#pragma unroll
        for (int p = 0; p < 2; p++) {
            if ((cg >> 1) == p) {
#pragma unroll
                for (int mf = 0; mf < 2; mf++) {
                    float li0 = Linv[qb + mf * 16 + r0];
                    float li1 = Linv[qb + mf * 16 + 8 + r0];
#pragma unroll
                    for (int nf = 0; nf < 8; nf++) {
                        int c  = (cg & 1) * 64 + nf * 8 + 2 * c2;
                        int q0 = qb + mf * 16 + r0;
                        Ostage[(c    ) * 132 + q0    ] = oacc[mf][nf][0] * li0;
                        Ostage[(c + 1) * 132 + q0    ] = oacc[mf][nf][1] * li0;
                        Ostage[(c    ) * 132 + q0 + 8] = oacc[mf][nf][2] * li1;
                        Ostage[(c + 1) * 132 + q0 + 8] = oacc[mf][nf][3] * li1;
                    }
                }
            }
            __syncthreads();
#pragma unroll
            for (int j = 0; j < 8; j++) {
                int idx = j * 512 + t;
                int c = idx >> 5, q4 = idx & 31;
                float4 o = *(float4*)&Ostage[c * 132 + q4 * 4];
                size_t gidx = ((size_t)(b * NC + ch0 + p * 128 + c)) * NN + n0 + q4 * 4;
                float4 xv = *(const float4*)(x + gidx);
                float4 rr;
                rr.x = gv2 * o.x + xv.x;
                rr.y = gv2 * o.y + xv.y;
                rr.z = gv2 * o.z + xv.z;
                rr.w = gv2 * o.w + xv.w;
                *(float4*)(out + gidx) = rr;
            }
            __syncthreads();
        }
    }
}

// =========================================================================
extern "C" void kernel_launch(void* const* d_in, const int* in_sizes, int n_in,
                              void* d_out, int out_size)
{
    (void)in_sizes; (void)n_in; (void)out_size;
    const float* x     = (const float*)d_in[0];
    const float* wq    = (const float*)d_in[1];
    const float* bq    = (const float*)d_in[2];
    const float* wk    = (const float*)d_in[3];
    const float* bk    = (const float*)d_in[4];
    const float* wv    = (const float*)d_in[5];
    const float* bv    = (const float*)d_in[6];
    const float* gamma = (const float*)d_in[7];
    float* out = (float*)d_out;

    cudaFuncSetAttribute(pam_proj, cudaFuncAttributeMaxDynamicSharedMemorySize, SMEM_PJ);
    cudaFuncSetAttribute(pam_sp,   cudaFuncAttributeMaxDynamicSharedMemorySize, SMEM_SP);
    cudaFuncSetAttribute(pam_pv,   cudaFuncAttributeMaxDynamicSharedMemorySize, SMEM_PV);

    pam_roundw<<<320, 256>>>(wq, wk, wv);
    pam_proj<<<dim3(NN / 128, 640 / 128, NB), 256, SMEM_PJ>>>(x, bq, bk, bv);
    pam_sp<<<dim3(NN / 128, NB), 512, SMEM_SP>>>();
    pam_pv<<<dim3(NN / 128, 1, NB), 512, SMEM_PV>>>(x, gamma, out);
}

// round 15
// speedup vs baseline: 1.4902x; 1.4902x over previous
#include <cuda_runtime.h>
#include <cuda_bf16.h>
#include <cstdint>

#define NB  4
#define NC  512
#define NN  4096
#define NCQ 64

// ---------------- device scratch ----------------
__device__ float g_Wr[640 * NC];                     // rounded unified [wq;wk;wv]
__device__ float g_Q[NB * NN * NCQ];                 // [b][n][k] tf32-rounded
__device__ float g_K[NB * NN * NCQ];                 // [b][m][k] tf32-rounded
__device__ __nv_bfloat16 g_Vh[(size_t)NB * NN * NC]; // [b][m][c] bf16
__device__ __nv_bfloat16 g_P[(size_t)NB * NN * NN];  // [b][q][m] bf16, 134 MB
__device__ float g_L[NB * NN];                       // 1 / sum(exp(s-20))

__device__ __forceinline__ float f2tff(float v) {
    uint32_t t;
    asm("cvt.rna.tf32.f32 %0, %1;" : "=r"(t) : "f"(v));
    return __uint_as_float(t);
}
__device__ __forceinline__ uint32_t f2tffu(float v) {
    uint32_t t;
    asm("cvt.rna.tf32.f32 %0, %1;" : "=r"(t) : "f"(v));
    return t;
}

__device__ __forceinline__ void mma8(float c[4],
                                     uint32_t a0, uint32_t a1, uint32_t a2, uint32_t a3,
                                     uint32_t b0, uint32_t b1) {
    asm volatile(
        "mma.sync.aligned.m16n8k8.row.col.f32.tf32.tf32.f32 "
        "{%0,%1,%2,%3},{%4,%5,%6,%7},{%8,%9},{%0,%1,%2,%3};"
        : "+f"(c[0]), "+f"(c[1]), "+f"(c[2]), "+f"(c[3])
        : "r"(a0), "r"(a1), "r"(a2), "r"(a3), "r"(b0), "r"(b1));
}

__device__ __forceinline__ void mma16(float c[4], const uint32_t a[4],
                                      uint32_t b0, uint32_t b1) {
    asm volatile(
        "mma.sync.aligned.m16n8k16.row.col.f32.bf16.bf16.f32 "
        "{%0,%1,%2,%3},{%4,%5,%6,%7},{%8,%9},{%0,%1,%2,%3};"
        : "+f"(c[0]), "+f"(c[1]), "+f"(c[2]), "+f"(c[3])
        : "r"(a[0]), "r"(a[1]), "r"(a[2]), "r"(a[3]), "r"(b0), "r"(b1));
}

__device__ __forceinline__ void ldsm4(uint32_t r[4], uint32_t addr) {
    asm volatile("ldmatrix.sync.aligned.m8n8.x4.shared.b16 {%0,%1,%2,%3},[%4];"
                 : "=r"(r[0]), "=r"(r[1]), "=r"(r[2]), "=r"(r[3]) : "r"(addr));
}
__device__ __forceinline__ void ldsm4t(uint32_t r[4], uint32_t addr) {
    asm volatile("ldmatrix.sync.aligned.m8n8.x4.trans.shared.b16 {%0,%1,%2,%3},[%4];"
                 : "=r"(r[0]), "=r"(r[1]), "=r"(r[2]), "=r"(r[3]) : "r"(addr));
}
__device__ __forceinline__ void cpa16(uint32_t s, const void* g) {
    asm volatile("cp.async.cg.shared.global [%0],[%1],16;" :: "r"(s), "l"(g));
}

// =========================================================================
// Kernel 0: pre-round W (once) into unified g_Wr[o][c], o in [0,640).
// =========================================================================
__global__ __launch_bounds__(256) void pam_roundw(
    const float* __restrict__ wq, const float* __restrict__ wk,
    const float* __restrict__ wv)
{
    int i = blockIdx.x * 256 + threadIdx.x;      // float4 index, 81920 total
    int p = i * 4;
    int o = p >> 9, c = p & 511;
    const float* src = (o < 64) ? (wq + (size_t)o * NC + c)
                     : (o < 128) ? (wk + (size_t)(o - 64) * NC + c)
                                 : (wv + (size_t)(o - 128) * NC + c);
    float4 v = *reinterpret_cast<const float4*>(src);
    v.x = f2tff(v.x); v.y = f2tff(v.y); v.z = f2tff(v.z); v.w = f2tff(v.w);
    *reinterpret_cast<float4*>(g_Wr + p) = v;
}

// =========================================================================
// Kernel 1: fused QKV projection (round-11 passing version, unchanged).
// =========================================================================
#define PJ_WS    33792
#define SMEM_PJ  70656

__global__ __launch_bounds__(256) void pam_proj(
    const float* __restrict__ x,
    const float* __restrict__ bq, const float* __restrict__ bk,
    const float* __restrict__ bv)
{
    extern __shared__ char sm[];
    uint32_t sb = (uint32_t)__cvta_generic_to_shared(sm);
    const uint32_t AsA = sb, WsA = sb + PJ_WS;

    const int b  = blockIdx.z;
    const int n0 = blockIdx.x * 128;
    const int oc = blockIdx.y * 128;
    const int t    = threadIdx.x;
    const int lane = t & 31;
    const int wid  = t >> 5;
    const int mg = wid & 3, og = wid >> 2;
    const int m0 = mg * 32, o0 = og * 64;
    const int r0 = lane >> 2, c2 = lane & 3;

    const int wr  = ((lane >> 4) & 1) * 8 + (lane & 7);
    const int wk2 = ((lane >> 3) & 1) * 4;

    {
#pragma unroll
        for (int r = 0; r < 4; r++) {
            int idx = t + 256 * r;
            int kk = idx >> 5, j4 = idx & 31;
            cpa16(AsA + kk * 528 + j4 * 16,
                  x + ((size_t)(b * NC + kk)) * NN + n0 + j4 * 4);
        }
#pragma unroll
        for (int r = 0; r < 4; r++) {
            int idx = t + 256 * r;
            int row = idx >> 3, f4 = idx & 7;
            cpa16(WsA + row * 144 + f4 * 16,
                  g_Wr + (size_t)(oc + row) * NC + f4 * 4);
        }
        asm volatile("cp.async.commit_group;" ::: "memory");
    }

    float acc[2][8][4];
#pragma unroll
    for (int mf = 0; mf < 2; mf++)
#pragma unroll
        for (int nf = 0; nf < 8; nf++)
#pragma unroll
            for (int e = 0; e < 4; e++) acc[mf][nf][e] = 0.f;

    for (int it = 0; it < 16; it++) {
        const int buf = it & 1;
        if (it < 15) {
            const int nb = (it + 1) & 1, kc = (it + 1) * 32;
#pragma unroll
            for (int r = 0; r < 4; r++) {
                int idx = t + 256 * r;
                int kk = idx >> 5, j4 = idx & 31;
                cpa16(AsA + nb * 16896 + kk * 528 + j4 * 16,
                      x + ((size_t)(b * NC + kc + kk)) * NN + n0 + j4 * 4);
            }
#pragma unroll
            for (int r = 0; r < 4; r++) {
                int idx = t + 256 * r;
                int row = idx >> 3, f4 = idx & 7;
                cpa16(WsA + nb * 18432 + row * 144 + f4 * 16,
                      g_Wr + (size_t)(oc + row) * NC + kc + f4 * 4);
            }
            asm volatile("cp.async.commit_group;" ::: "memory");
            asm volatile("cp.async.wait_group 1;" ::: "memory");
        } else {
            asm volatile("cp.async.wait_group 0;" ::: "memory");
        }
        __syncthreads();

        const float* AsB = (const float*)(sm + buf * 16896);
        const uint32_t WsB = WsA + buf * 18432;

#pragma unroll
        for (int kq = 0; kq < 32; kq += 8) {
            uint32_t a[2][4];
#pragma unroll
            for (int mf = 0; mf < 2; mf++) {
                const float* Ab = AsB + (kq + c2) * 132 + m0 + mf * 16 + r0;
                a[mf][0] = f2tffu(Ab[0]);
                a[mf][1] = f2tffu(Ab[8]);
                a[mf][2] = f2tffu(Ab[4 * 132]);
                a[mf][3] = f2tffu(Ab[4 * 132 + 8]);
            }
#pragma unroll
            for (int i = 0; i < 4; i++) {
                uint32_t wf[4];
                ldsm4(wf, WsB + (uint32_t)(o0 + i * 16 + wr) * 144 + (kq + wk2) * 4);
                mma8(acc[0][2 * i],     a[0][0], a[0][1], a[0][2], a[0][3], wf[0], wf[1]);
                mma8(acc[0][2 * i + 1], a[0][0], a[0][1], a[0][2], a[0][3], wf[2], wf[3]);
                mma8(acc[1][2 * i],     a[1][0], a[1][1], a[1][2], a[1][3], wf[0], wf[1]);
                mma8(acc[1][2 * i + 1], a[1][0], a[1][1], a[1][2], a[1][3], wf[2], wf[3]);
            }
        }
        __syncthreads();
    }

    const int c0 = 2 * (lane & 3);
#pragma unroll
    for (int mf = 0; mf < 2; mf++) {
#pragma unroll
        for (int nf = 0; nf < 8; nf++) {
#pragma unroll
            for (int e = 0; e < 4; e++) {
                int row = m0 + mf * 16 + r0 + ((e >= 2) ? 8 : 0);
                int col = o0 + (nf >> 1) * 16 + (nf & 1) * 8 + c0 + (e & 1);
                int o = oc + col;
                int n = n0 + row;
                if (o < 64) {
                    g_Q[((size_t)b * NN + n) * NCQ + o] = f2tff(acc[mf][nf][e] + bq[o]);
                } else if (o < 128) {
                    g_K[((size_t)b * NN + n) * NCQ + (o - 64)] = f2tff(acc[mf][nf][e] + bk[o - 64]);
                } else {
                    g_Vh[((size_t)b * NN + n) * NC + (o - 128)] =
                        __float2bfloat16(acc[mf][nf][e] + bv[o - 128]);
                }
            }
        }
    }
}

// =========================================================================
// Kernel 2: S = Q K^T once, P = exp(S-20) -> global bf16 via smem staging,
// Linv -> global. Grid 32 x 4 = 128 CTAs (round-11 passing version).
// =========================================================================
#define SP_KS    34816
#define SP_LP    69632
#define SP_PST   71680
#define SMEM_SP  90112

__global__ __launch_bounds__(512, 1) void pam_sp()
{
    extern __shared__ char sm[];
    float* Lpart = (float*)(sm + SP_LP);
    __nv_bfloat16* Pst = (__nv_bfloat16*)(sm + SP_PST);
    uint32_t sb = (uint32_t)__cvta_generic_to_shared(sm);
    const uint32_t QsA = sb, KsA = sb + SP_KS;

    const int b  = blockIdx.y;
    const int n0 = blockIdx.x * 128;
    const int t = threadIdx.x, lane = t & 31, wid = t >> 5;
    const int qs = wid >> 2, mg = wid & 3;
    const int qb = qs * 32;
    const int r0 = lane >> 2, c2 = lane & 3;

    const int qrow = (lane & 7) + (((lane >> 3) & 1) << 3);
    const int qkof = ((lane >> 4) & 1) * 4;
    const int krow = (lane & 7) + (((lane >> 4) & 1) << 3);
    const int kkof = ((lane >> 3) & 1) * 4;

    {
        const float* gq = g_Q + ((size_t)b * NN + n0) * NCQ;
#pragma unroll
        for (int r2 = 0; r2 < 4; r2++) {
            int cid = t + 512 * r2; int row = cid >> 4, c16 = cid & 15;
            cpa16(QsA + row * 272 + c16 * 16, gq + row * 64 + c16 * 4);
        }
        const float* gk = g_K + ((size_t)b * NN) * NCQ;
#pragma unroll
        for (int r2 = 0; r2 < 2; r2++) {
            int cid = t + 512 * r2; int row = cid >> 4, c16 = cid & 15;
            cpa16(KsA + row * 272 + c16 * 16, gk + row * 64 + c16 * 4);
        }
        asm volatile("cp.async.commit_group;" ::: "memory");
    }

    float Lacc[4] = {0.f, 0.f, 0.f, 0.f};
    __nv_bfloat16* gp = g_P + ((size_t)b * NN + n0) * NN;

    for (int mt = 0; mt < 64; mt++) {
        const int buf = mt & 1;
        if (mt < 63) {
            const int nb = (mt + 1) & 1;
            const float* gk = g_K + ((size_t)b * NN + (mt + 1) * 64) * NCQ;
#pragma unroll
            for (int r2 = 0; r2 < 2; r2++) {
                int cid = t + 512 * r2; int row = cid >> 4, c16 = cid & 15;
                cpa16(KsA + nb * 17408 + row * 272 + c16 * 16, gk + row * 64 + c16 * 4);
            }
            asm volatile("cp.async.commit_group;" ::: "memory");
            asm volatile("cp.async.wait_group 1;" ::: "memory");
        } else {
            asm volatile("cp.async.wait_group 0;" ::: "memory");
        }
        __syncthreads();

        const uint32_t KbA = KsA + buf * 17408;
        float sacc[2][2][4];
#pragma unroll
        for (int mf = 0; mf < 2; mf++)
#pragma unroll
            for (int nf = 0; nf < 2; nf++)
#pragma unroll
                for (int e = 0; e < 4; e++) sacc[mf][nf][e] = 0.f;

#pragma unroll
        for (int j = 0; j < 8; j++) {
            uint32_t kf[4];
            ldsm4(kf, KbA + (uint32_t)(mg * 16 + krow) * 272 + (j * 8 + kkof) * 4);
#pragma unroll
            for (int mf = 0; mf < 2; mf++) {
                uint32_t qf[4];
                ldsm4(qf, QsA + (uint32_t)(qb + mf * 16 + qrow) * 272 + (j * 8 + qkof) * 4);
                mma8(sacc[mf][0], qf[0], qf[1], qf[2], qf[3], kf[0], kf[1]);
                mma8(sacc[mf][1], qf[0], qf[1], qf[2], qf[3], kf[2], kf[3]);
            }
        }

#pragma unroll
        for (int mf = 0; mf < 2; mf++)
#pragma unroll
            for (int nf = 0; nf < 2; nf++)
#pragma unroll
                for (int h = 0; h < 2; h++) {
                    float e0 = __expf(sacc[mf][nf][2 * h]     - 20.f);
                    float e1 = __expf(sacc[mf][nf][2 * h + 1] - 20.f);
                    Lacc[mf * 2 + h] += e0 + e1;
                    uint32_t pk;
                    asm("cvt.rn.bf16x2.f32 %0, %1, %2;" : "=r"(pk) : "f"(e1), "f"(e0));
                    int q = qb + mf * 16 + h * 8 + r0;
                    int m = mg * 16 + nf * 8 + 2 * c2;
                    *(uint32_t*)((char*)Pst + q * 144 + m * 2) = pk;
                }
        __syncthreads();

#pragma unroll
        for (int r2 = 0; r2 < 2; r2++) {
            int idx = t + 512 * r2;
            int row = idx >> 3, ch = idx & 7;
            *(float4*)(gp + (size_t)row * NN + mt * 64 + ch * 8) =
                *(const float4*)((const char*)Pst + row * 144 + ch * 16);
        }
    }

#pragma unroll
    for (int i = 0; i < 4; i++) {
        float v = Lacc[i];
        v += __shfl_xor_sync(0xffffffffu, v, 1);
        v += __shfl_xor_sync(0xffffffffu, v, 2);
        if (c2 == 0) Lpart[mg * 128 + qb + (i >> 1) * 16 + (i & 1) * 8 + r0] = v;
    }
    __syncthreads();
    if (t < 128)
        g_L[(size_t)b * NN + n0 + t] =
            1.f / (Lpart[t] + Lpart[128 + t] + Lpart[256 + t] + Lpart[384 + t]);
}

// =========================================================================
// Kernel 3: O = P @ V + epilogue. 64-q CTAs, 256 threads, 2 CTAs/SM so
// barrier/wait bubbles of one CTA are covered by the other.
// Warp (qs = wid>>2 in {0,1}, cg = wid&3): tile 32q x 64c (oacc 64 regs).
// P back on the LDSM path (smem-staged). 2-stage pipeline, SAFE ordering:
// wait -> sync -> prefetch(mt+1) -> compute(mt). One sync per tile.
// Grid 64 x 1 x 4 = 256 CTAs = one wave at 2/SM.
// Smem: Ps bf16[2][64][72] | Vs bf16[2][64][264] | Linv f32[64]
//       (Ostage f32[128][68] overlays Vs in epilogue)
// =========================================================================
#define PV_VS    18432
#define PV_LI    86016
#define SMEM_PV  86272

__global__ __launch_bounds__(256, 2) void pam_pv(
    const float* __restrict__ x,
    const float* __restrict__ gamma,
    float* __restrict__ out)
{
    extern __shared__ char sm[];
    float* Linv   = (float*)(sm + PV_LI);
    float* Ostage = (float*)(sm + PV_VS);
    uint32_t sb = (uint32_t)__cvta_generic_to_shared(sm);
    const uint32_t PsA = sb, VsA = sb + PV_VS;

    const int b   = blockIdx.z;
    const int n0  = blockIdx.x * 64;
    const int t = threadIdx.x, lane = t & 31, wid = t >> 5;
    const int qs = wid >> 2, cg = wid & 3;
    const int qb = qs * 32;
    const int r0 = lane >> 2, c2 = lane & 3;

    const __nv_bfloat16* __restrict__ gp = g_P + ((size_t)b * NN + n0) * NN;

    if (t < 64) Linv[t] = g_L[(size_t)b * NN + n0 + t];

    const int ar = (lane & 7) + ((lane >> 3) & 1) * 8;
    const int ly = (lane >> 4) * 8;
    const int lx = lane & 15;
    const float gv2 = gamma[0];

    for (int p2 = 0; p2 < 2; p2++) {
        const int ch0 = p2 * 256;
        const __nv_bfloat16* gv = g_Vh + ((size_t)b * NN) * NC + ch0;

        // prologue: tile 0 (P 64x64, V 64x256), one commit group
        {
#pragma unroll
            for (int r2 = 0; r2 < 2; r2++) {
                int cid = t + 256 * r2; int row = cid >> 3, ch = cid & 7;
                cpa16(PsA + row * 144 + ch * 16, gp + (size_t)row * NN + ch * 8);
            }
#pragma unroll
            for (int r2 = 0; r2 < 8; r2++) {
                int cid = t + 256 * r2; int row = cid >> 5, c16 = cid & 31;
                cpa16(VsA + row * 528 + c16 * 16, gv + (size_t)row * NC + c16 * 8);
            }
            asm volatile("cp.async.commit_group;" ::: "memory");
        }

        float oacc[2][8][4];
#pragma unroll
        for (int mf = 0; mf < 2; mf++)
#pragma unroll
            for (int nf = 0; nf < 8; nf++)
#pragma unroll
                for (int e = 0; e < 4; e++) oacc[mf][nf][e] = 0.f;

        for (int mt = 0; mt < 64; mt++) {
            asm volatile("cp.async.wait_group 0;" ::: "memory");
            __syncthreads();   // tile mt visible; all warps done with slot (mt+1)&1

            // prefetch tile mt+1 (overlaps with compute of mt)
            if (mt < 63) {
                const int sl = (mt + 1) & 1, m1 = (mt + 1) * 64;
#pragma unroll
                for (int r2 = 0; r2 < 2; r2++) {
                    int cid = t + 256 * r2; int row = cid >> 3, ch = cid & 7;
                    cpa16(PsA + sl * 9216 + row * 144 + ch * 16,
                          gp + (size_t)row * NN + m1 + ch * 8);
                }
#pragma unroll
                for (int r2 = 0; r2 < 8; r2++) {
                    int cid = t + 256 * r2; int row = cid >> 5, c16 = cid & 31;
                    cpa16(VsA + sl * 33792 + row * 528 + c16 * 16,
                          gv + (size_t)(m1 + row) * NC + c16 * 8);
                }
                asm volatile("cp.async.commit_group;" ::: "memory");
            }

            const uint32_t Pb = PsA + (mt & 1) * 9216;
            const uint32_t Vb = VsA + (mt & 1) * 33792;
#pragma unroll
            for (int ks = 0; ks < 4; ks++) {
                const int k0 = ks * 16;
                uint32_t a[2][4];
#pragma unroll
                for (int mf = 0; mf < 2; mf++)
                    ldsm4(a[mf], Pb + (uint32_t)(qb + mf * 16 + ar) * 144 + (k0 + ly) * 2);
#pragma unroll
                for (int cb = 0; cb < 4; cb++) {
                    uint32_t bb[4];
                    ldsm4t(bb, Vb + (uint32_t)(k0 + lx) * 528 + (cg * 64 + cb * 16 + ly) * 2);
                    mma16(oacc[0][cb * 2],     a[0], bb[0], bb[1]);
                    mma16(oacc[0][cb * 2 + 1], a[0], bb[2], bb[3]);
                    mma16(oacc[1][cb * 2],     a[1], bb[0], bb[1]);
                    mma16(oacc[1][cb * 2 + 1], a[1], bb[2], bb[3]);
                }
            }
        }
        __syncthreads();   // all reads of Ps/Vs done before Ostage overlays Vs

        // epilogue: two 128-channel passes through Ostage, coalesced writes
#pragma unroll
        for (int p = 0; p < 2; p++) {
            if ((cg >> 1) == p) {
#pragma unroll
                for (int mf = 0; mf < 2; mf++) {
                    float li0 = Linv[qb + mf * 16 + r0];
                    float li1 = Linv[qb + mf * 16 + 8 + r0];
#pragma unroll
                    for (int nf = 0; nf < 8; nf++) {
                        int c  = (cg & 1) * 64 + nf * 8 + 2 * c2;
                        int q0 = qb + mf * 16 + r0;
                        Ostage[(c    ) * 68 + q0    ] = oacc[mf][nf][0] * li0;
                        Ostage[(c + 1) * 68 + q0    ] = oacc[mf][nf][1] * li0;
                        Ostage[(c    ) * 68 + q0 + 8] = oacc[mf][nf][2] * li1;
                        Ostage[(c + 1) * 68 + q0 + 8] = oacc[mf][nf][3] * li1;
                    }
                }
            }
            __syncthreads();
#pragma unroll
            for (int j = 0; j < 8; j++) {
                int idx = j * 256 + t;
                int c = idx >> 4, q4 = idx & 15;
                float4 o = *(float4*)&Ostage[c * 68 + q4 * 4];
                size_t gidx = ((size_t)(b * NC + ch0 + p * 128 + c)) * NN + n0 + q4 * 4;
                float4 xv = *(const float4*)(x + gidx);
                float4 rr;
                rr.x = gv2 * o.x + xv.x;
                rr.y = gv2 * o.y + xv.y;
                rr.z = gv2 * o.z + xv.z;
                rr.w = gv2 * o.w + xv.w;
                *(float4*)(out + gidx) = rr;
            }
            __syncthreads();
        }
    }
}

// =========================================================================
extern "C" void kernel_launch(void* const* d_in, const int* in_sizes, int n_in,
                              void* d_out, int out_size)
{
    (void)in_sizes; (void)n_in; (void)out_size;
    const float* x     = (const float*)d_in[0];
    const float* wq    = (const float*)d_in[1];
    const float* bq    = (const float*)d_in[2];
    const float* wk    = (const float*)d_in[3];
    const float* bk    = (const float*)d_in[4];
    const float* wv    = (const float*)d_in[5];
    const float* bv    = (const float*)d_in[6];
    const float* gamma = (const float*)d_in[7];
    float* out = (float*)d_out;

    cudaFuncSetAttribute(pam_proj, cudaFuncAttributeMaxDynamicSharedMemorySize, SMEM_PJ);
    cudaFuncSetAttribute(pam_sp,   cudaFuncAttributeMaxDynamicSharedMemorySize, SMEM_SP);
    cudaFuncSetAttribute(pam_pv,   cudaFuncAttributeMaxDynamicSharedMemorySize, SMEM_PV);

    pam_roundw<<<320, 256>>>(wq, wk, wv);
    pam_proj<<<dim3(NN / 128, 640 / 128, NB), 256, SMEM_PJ>>>(x, bq, bk, bv);
    pam_sp<<<dim3(NN / 128, NB), 512, SMEM_SP>>>();
    pam_pv<<<dim3(NN / 64, 1, NB), 256, SMEM_PV>>>(x, gamma, out);
}

// round 16
// speedup vs baseline: 1.5594x; 1.0465x over previous
#include <cuda_runtime.h>
#include <cuda_bf16.h>
#include <cstdint>

#define NB  4
#define NC  512
#define NN  4096
#define NCQ 64

// ---------------- device scratch ----------------
__device__ float g_Wr[640 * NC];                     // rounded unified [wq;wk;wv]
__device__ float g_Q[NB * NN * NCQ];                 // [b][n][k] tf32-rounded
__device__ float g_K[NB * NN * NCQ];                 // [b][m][k] tf32-rounded
__device__ __nv_bfloat16 g_Vh[(size_t)NB * NN * NC]; // [b][m][c] bf16
__device__ __nv_bfloat16 g_P[(size_t)NB * NN * NN];  // [b][q][m] bf16, 134 MB
__device__ float g_L[NB * NN];                       // 1 / sum(exp(s-20))

__device__ __forceinline__ float f2tff(float v) {
    uint32_t t;
    asm("cvt.rna.tf32.f32 %0, %1;" : "=r"(t) : "f"(v));
    return __uint_as_float(t);
}
__device__ __forceinline__ uint32_t f2tffu(float v) {
    uint32_t t;
    asm("cvt.rna.tf32.f32 %0, %1;" : "=r"(t) : "f"(v));
    return t;
}

__device__ __forceinline__ void mma8(float c[4],
                                     uint32_t a0, uint32_t a1, uint32_t a2, uint32_t a3,
                                     uint32_t b0, uint32_t b1) {
    asm volatile(
        "mma.sync.aligned.m16n8k8.row.col.f32.tf32.tf32.f32 "
        "{%0,%1,%2,%3},{%4,%5,%6,%7},{%8,%9},{%0,%1,%2,%3};"
        : "+f"(c[0]), "+f"(c[1]), "+f"(c[2]), "+f"(c[3])
        : "r"(a0), "r"(a1), "r"(a2), "r"(a3), "r"(b0), "r"(b1));
}

__device__ __forceinline__ void mma16(float c[4], const uint32_t a[4],
                                      uint32_t b0, uint32_t b1) {
    asm volatile(
        "mma.sync.aligned.m16n8k16.row.col.f32.bf16.bf16.f32 "
        "{%0,%1,%2,%3},{%4,%5,%6,%7},{%8,%9},{%0,%1,%2,%3};"
        : "+f"(c[0]), "+f"(c[1]), "+f"(c[2]), "+f"(c[3])
        : "r"(a[0]), "r"(a[1]), "r"(a[2]), "r"(a[3]), "r"(b0), "r"(b1));
}

__device__ __forceinline__ void ldsm4(uint32_t r[4], uint32_t addr) {
    asm volatile("ldmatrix.sync.aligned.m8n8.x4.shared.b16 {%0,%1,%2,%3},[%4];"
                 : "=r"(r[0]), "=r"(r[1]), "=r"(r[2]), "=r"(r[3]) : "r"(addr));
}
__device__ __forceinline__ void ldsm4t(uint32_t r[4], uint32_t addr) {
    asm volatile("ldmatrix.sync.aligned.m8n8.x4.trans.shared.b16 {%0,%1,%2,%3},[%4];"
                 : "=r"(r[0]), "=r"(r[1]), "=r"(r[2]), "=r"(r[3]) : "r"(addr));
}
__device__ __forceinline__ void cpa16(uint32_t s, const void* g) {
    asm volatile("cp.async.cg.shared.global [%0],[%1],16;" :: "r"(s), "l"(g));
}

// =========================================================================
// Kernel 0: pre-round W (once) into unified g_Wr[o][c], o in [0,640).
// =========================================================================
__global__ __launch_bounds__(256) void pam_roundw(
    const float* __restrict__ wq, const float* __restrict__ wk,
    const float* __restrict__ wv)
{
    int i = blockIdx.x * 256 + threadIdx.x;      // float4 index, 81920 total
    int p = i * 4;
    int o = p >> 9, c = p & 511;
    const float* src = (o < 64) ? (wq + (size_t)o * NC + c)
                     : (o < 128) ? (wk + (size_t)(o - 64) * NC + c)
                                 : (wv + (size_t)(o - 128) * NC + c);
    float4 v = *reinterpret_cast<const float4*>(src);
    v.x = f2tff(v.x); v.y = f2tff(v.y); v.z = f2tff(v.z); v.w = f2tff(v.w);
    *reinterpret_cast<float4*>(g_Wr + p) = v;
}

// =========================================================================
// Kernel 1: fused QKV projection (round-11 passing version, unchanged).
// =========================================================================
#define PJ_WS    33792
#define SMEM_PJ  70656

__global__ __launch_bounds__(256) void pam_proj(
    const float* __restrict__ x,
    const float* __restrict__ bq, const float* __restrict__ bk,
    const float* __restrict__ bv)
{
    extern __shared__ char sm[];
    uint32_t sb = (uint32_t)__cvta_generic_to_shared(sm);
    const uint32_t AsA = sb, WsA = sb + PJ_WS;

    const int b  = blockIdx.z;
    const int n0 = blockIdx.x * 128;
    const int oc = blockIdx.y * 128;
    const int t    = threadIdx.x;
    const int lane = t & 31;
    const int wid  = t >> 5;
    const int mg = wid & 3, og = wid >> 2;
    const int m0 = mg * 32, o0 = og * 64;
    const int r0 = lane >> 2, c2 = lane & 3;

    const int wr  = ((lane >> 4) & 1) * 8 + (lane & 7);
    const int wk2 = ((lane >> 3) & 1) * 4;

    {
#pragma unroll
        for (int r = 0; r < 4; r++) {
            int idx = t + 256 * r;
            int kk = idx >> 5, j4 = idx & 31;
            cpa16(AsA + kk * 528 + j4 * 16,
                  x + ((size_t)(b * NC + kk)) * NN + n0 + j4 * 4);
        }
#pragma unroll
        for (int r = 0; r < 4; r++) {
            int idx = t + 256 * r;
            int row = idx >> 3, f4 = idx & 7;
            cpa16(WsA + row * 144 + f4 * 16,
                  g_Wr + (size_t)(oc + row) * NC + f4 * 4);
        }
        asm volatile("cp.async.commit_group;" ::: "memory");
    }

    float acc[2][8][4];
#pragma unroll
    for (int mf = 0; mf < 2; mf++)
#pragma unroll
        for (int nf = 0; nf < 8; nf++)
#pragma unroll
            for (int e = 0; e < 4; e++) acc[mf][nf][e] = 0.f;

    for (int it = 0; it < 16; it++) {
        const int buf = it & 1;
        if (it < 15) {
            const int nb = (it + 1) & 1, kc = (it + 1) * 32;
#pragma unroll
            for (int r = 0; r < 4; r++) {
                int idx = t + 256 * r;
                int kk = idx >> 5, j4 = idx & 31;
                cpa16(AsA + nb * 16896 + kk * 528 + j4 * 16,
                      x + ((size_t)(b * NC + kc + kk)) * NN + n0 + j4 * 4);
            }
#pragma unroll
            for (int r = 0; r < 4; r++) {
                int idx = t + 256 * r;
                int row = idx >> 3, f4 = idx & 7;
                cpa16(WsA + nb * 18432 + row * 144 + f4 * 16,
                      g_Wr + (size_t)(oc + row) * NC + kc + f4 * 4);
            }
            asm volatile("cp.async.commit_group;" ::: "memory");
            asm volatile("cp.async.wait_group 1;" ::: "memory");
        } else {
            asm volatile("cp.async.wait_group 0;" ::: "memory");
        }
        __syncthreads();

        const float* AsB = (const float*)(sm + buf * 16896);
        const uint32_t WsB = WsA + buf * 18432;

#pragma unroll
        for (int kq = 0; kq < 32; kq += 8) {
            uint32_t a[2][4];
#pragma unroll
            for (int mf = 0; mf < 2; mf++) {
                const float* Ab = AsB + (kq + c2) * 132 + m0 + mf * 16 + r0;
                a[mf][0] = f2tffu(Ab[0]);
                a[mf][1] = f2tffu(Ab[8]);
                a[mf][2] = f2tffu(Ab[4 * 132]);
                a[mf][3] = f2tffu(Ab[4 * 132 + 8]);
            }
#pragma unroll
            for (int i = 0; i < 4; i++) {
                uint32_t wf[4];
                ldsm4(wf, WsB + (uint32_t)(o0 + i * 16 + wr) * 144 + (kq + wk2) * 4);
                mma8(acc[0][2 * i],     a[0][0], a[0][1], a[0][2], a[0][3], wf[0], wf[1]);
                mma8(acc[0][2 * i + 1], a[0][0], a[0][1], a[0][2], a[0][3], wf[2], wf[3]);
                mma8(acc[1][2 * i],     a[1][0], a[1][1], a[1][2], a[1][3], wf[0], wf[1]);
                mma8(acc[1][2 * i + 1], a[1][0], a[1][1], a[1][2], a[1][3], wf[2], wf[3]);
            }
        }
        __syncthreads();
    }

    const int c0 = 2 * (lane & 3);
#pragma unroll
    for (int mf = 0; mf < 2; mf++) {
#pragma unroll
        for (int nf = 0; nf < 8; nf++) {
#pragma unroll
            for (int e = 0; e < 4; e++) {
                int row = m0 + mf * 16 + r0 + ((e >= 2) ? 8 : 0);
                int col = o0 + (nf >> 1) * 16 + (nf & 1) * 8 + c0 + (e & 1);
                int o = oc + col;
                int n = n0 + row;
                if (o < 64) {
                    g_Q[((size_t)b * NN + n) * NCQ + o] = f2tff(acc[mf][nf][e] + bq[o]);
                } else if (o < 128) {
                    g_K[((size_t)b * NN + n) * NCQ + (o - 64)] = f2tff(acc[mf][nf][e] + bk[o - 64]);
                } else {
                    g_Vh[((size_t)b * NN + n) * NC + (o - 128)] =
                        __float2bfloat16(acc[mf][nf][e] + bv[o - 128]);
                }
            }
        }
    }
}

// =========================================================================
// Kernel 2: S = Q K^T once, P = exp(S-20) -> global bf16 via smem staging,
// Linv -> global. Grid 32 x 4 = 128 CTAs (round-11 passing version).
// =========================================================================
#define SP_KS    34816
#define SP_LP    69632
#define SP_PST   71680
#define SMEM_SP  90112

__global__ __launch_bounds__(512, 1) void pam_sp()
{
    extern __shared__ char sm[];
    float* Lpart = (float*)(sm + SP_LP);
    __nv_bfloat16* Pst = (__nv_bfloat16*)(sm + SP_PST);
    uint32_t sb = (uint32_t)__cvta_generic_to_shared(sm);
    const uint32_t QsA = sb, KsA = sb + SP_KS;

    const int b  = blockIdx.y;
    const int n0 = blockIdx.x * 128;
    const int t = threadIdx.x, lane = t & 31, wid = t >> 5;
    const int qs = wid >> 2, mg = wid & 3;
    const int qb = qs * 32;
    const int r0 = lane >> 2, c2 = lane & 3;

    const int qrow = (lane & 7) + (((lane >> 3) & 1) << 3);
    const int qkof = ((lane >> 4) & 1) * 4;
    const int krow = (lane & 7) + (((lane >> 4) & 1) << 3);
    const int kkof = ((lane >> 3) & 1) * 4;

    {
        const float* gq = g_Q + ((size_t)b * NN + n0) * NCQ;
#pragma unroll
        for (int r2 = 0; r2 < 4; r2++) {
            int cid = t + 512 * r2; int row = cid >> 4, c16 = cid & 15;
            cpa16(QsA + row * 272 + c16 * 16, gq + row * 64 + c16 * 4);
        }
        const float* gk = g_K + ((size_t)b * NN) * NCQ;
#pragma unroll
        for (int r2 = 0; r2 < 2; r2++) {
            int cid = t + 512 * r2; int row = cid >> 4, c16 = cid & 15;
            cpa16(KsA + row * 272 + c16 * 16, gk + row * 64 + c16 * 4);
        }
        asm volatile("cp.async.commit_group;" ::: "memory");
    }

    float Lacc[4] = {0.f, 0.f, 0.f, 0.f};
    __nv_bfloat16* gp = g_P + ((size_t)b * NN + n0) * NN;

    for (int mt = 0; mt < 64; mt++) {
        const int buf = mt & 1;
        if (mt < 63) {
            const int nb = (mt + 1) & 1;
            const float* gk = g_K + ((size_t)b * NN + (mt + 1) * 64) * NCQ;
#pragma unroll
            for (int r2 = 0; r2 < 2; r2++) {
                int cid = t + 512 * r2; int row = cid >> 4, c16 = cid & 15;
                cpa16(KsA + nb * 17408 + row * 272 + c16 * 16, gk + row * 64 + c16 * 4);
            }
            asm volatile("cp.async.commit_group;" ::: "memory");
            asm volatile("cp.async.wait_group 1;" ::: "memory");
        } else {
            asm volatile("cp.async.wait_group 0;" ::: "memory");
        }
        __syncthreads();

        const uint32_t KbA = KsA + buf * 17408;
        float sacc[2][2][4];
#pragma unroll
        for (int mf = 0; mf < 2; mf++)
#pragma unroll
            for (int nf = 0; nf < 2; nf++)
#pragma unroll
                for (int e = 0; e < 4; e++) sacc[mf][nf][e] = 0.f;

#pragma unroll
        for (int j = 0; j < 8; j++) {
            uint32_t kf[4];
            ldsm4(kf, KbA + (uint32_t)(mg * 16 + krow) * 272 + (j * 8 + kkof) * 4);
#pragma unroll
            for (int mf = 0; mf < 2; mf++) {
                uint32_t qf[4];
                ldsm4(qf, QsA + (uint32_t)(qb + mf * 16 + qrow) * 272 + (j * 8 + qkof) * 4);
                mma8(sacc[mf][0], qf[0], qf[1], qf[2], qf[3], kf[0], kf[1]);
                mma8(sacc[mf][1], qf[0], qf[1], qf[2], qf[3], kf[2], kf[3]);
            }
        }

#pragma unroll
        for (int mf = 0; mf < 2; mf++)
#pragma unroll
            for (int nf = 0; nf < 2; nf++)
#pragma unroll
                for (int h = 0; h < 2; h++) {
                    float e0 = __expf(sacc[mf][nf][2 * h]     - 20.f);
                    float e1 = __expf(sacc[mf][nf][2 * h + 1] - 20.f);
                    Lacc[mf * 2 + h] += e0 + e1;
                    uint32_t pk;
                    asm("cvt.rn.bf16x2.f32 %0, %1, %2;" : "=r"(pk) : "f"(e1), "f"(e0));
                    int q = qb + mf * 16 + h * 8 + r0;
                    int m = mg * 16 + nf * 8 + 2 * c2;
                    *(uint32_t*)((char*)Pst + q * 144 + m * 2) = pk;
                }
        __syncthreads();

#pragma unroll
        for (int r2 = 0; r2 < 2; r2++) {
            int idx = t + 512 * r2;
            int row = idx >> 3, ch = idx & 7;
            *(float4*)(gp + (size_t)row * NN + mt * 64 + ch * 8) =
                *(const float4*)((const char*)Pst + row * 144 + ch * 16);
        }
    }

#pragma unroll
    for (int i = 0; i < 4; i++) {
        float v = Lacc[i];
        v += __shfl_xor_sync(0xffffffffu, v, 1);
        v += __shfl_xor_sync(0xffffffffu, v, 2);
        if (c2 == 0) Lpart[mg * 128 + qb + (i >> 1) * 16 + (i & 1) * 8 + r0] = v;
    }
    __syncthreads();
    if (t < 128)
        g_L[(size_t)b * NN + n0 + t] =
            1.f / (Lpart[t] + Lpart[128 + t] + Lpart[256 + t] + Lpart[384 + t]);
}

// =========================================================================
// Kernel 3: O = P @ V + epilogue. Round-11 shape (512 thr, 128q, 1 CTA/SM,
// persistent over 2 channel halves) but KEY TILE 128: 32 sync/wait pairs
// instead of 64. Safe 2-stage pipeline: wait -> sync -> prefetch -> compute.
// Smem: Ps bf16[2][128][136] | Vs bf16[2][128][264] | Linv f32[128]
//       (Ostage f32[128][132] overlays Ps in epilogue)
// =========================================================================
#define PV_VS    69632
#define PV_LI    204800
#define SMEM_PV  205312

__global__ __launch_bounds__(512, 1) void pam_pv(
    const float* __restrict__ x,
    const float* __restrict__ gamma,
    float* __restrict__ out)
{
    extern __shared__ char sm[];
    float* Linv   = (float*)(sm + PV_LI);
    float* Ostage = (float*)sm;
    uint32_t sb = (uint32_t)__cvta_generic_to_shared(sm);
    const uint32_t PsA = sb, VsA = sb + PV_VS;

    const int b   = blockIdx.z;
    const int n0  = blockIdx.x * 128;
    const int t = threadIdx.x, lane = t & 31, wid = t >> 5;
    const int qs = wid >> 2, cg = wid & 3;
    const int qb = qs * 32;
    const int r0 = lane >> 2, c2 = lane & 3;

    const __nv_bfloat16* __restrict__ gp = g_P + ((size_t)b * NN + n0) * NN;

    if (t < 128) Linv[t] = g_L[(size_t)b * NN + n0 + t];

    const int ar = (lane & 7) + ((lane >> 3) & 1) * 8;
    const int ly = (lane >> 4) * 8;
    const int lx = lane & 15;
    const float gv2 = gamma[0];

    for (int p2 = 0; p2 < 2; p2++) {
        const int ch0 = p2 * 256;
        const __nv_bfloat16* gv = g_Vh + ((size_t)b * NN) * NC + ch0;

        // prologue: tile 0 (P 128x128, V 128x256), one commit group
        {
#pragma unroll
            for (int r2 = 0; r2 < 4; r2++) {
                int cid = t + 512 * r2; int row = cid >> 4, ch = cid & 15;
                cpa16(PsA + row * 272 + ch * 16, gp + (size_t)row * NN + ch * 8);
            }
#pragma unroll
            for (int r2 = 0; r2 < 8; r2++) {
                int cid = t + 512 * r2; int row = cid >> 5, c16 = cid & 31;
                cpa16(VsA + row * 528 + c16 * 16, gv + (size_t)row * NC + c16 * 8);
            }
            asm volatile("cp.async.commit_group;" ::: "memory");
        }

        float oacc[2][8][4];
#pragma unroll
        for (int mf = 0; mf < 2; mf++)
#pragma unroll
            for (int nf = 0; nf < 8; nf++)
#pragma unroll
                for (int e = 0; e < 4; e++) oacc[mf][nf][e] = 0.f;

        for (int mt = 0; mt < 32; mt++) {
            asm volatile("cp.async.wait_group 0;" ::: "memory");
            __syncthreads();   // tile mt visible; all warps done with other slot

            // prefetch tile mt+1 into other slot (overlaps with compute of mt)
            if (mt < 31) {
                const int sl = (mt + 1) & 1, m1 = (mt + 1) * 128;
#pragma unroll
                for (int r2 = 0; r2 < 4; r2++) {
                    int cid = t + 512 * r2; int row = cid >> 4, ch = cid & 15;
                    cpa16(PsA + sl * 34816 + row * 272 + ch * 16,
                          gp + (size_t)row * NN + m1 + ch * 8);
                }
#pragma unroll
                for (int r2 = 0; r2 < 8; r2++) {
                    int cid = t + 512 * r2; int row = cid >> 5, c16 = cid & 31;
                    cpa16(VsA + sl * 67584 + row * 528 + c16 * 16,
                          gv + (size_t)(m1 + row) * NC + c16 * 8);
                }
                asm volatile("cp.async.commit_group;" ::: "memory");
            }

            const uint32_t Pb = PsA + (mt & 1) * 34816;
            const uint32_t Vb = VsA + (mt & 1) * 67584;
#pragma unroll
            for (int ks = 0; ks < 8; ks++) {
                const int k0 = ks * 16;
                uint32_t a[2][4];
#pragma unroll
                for (int mf = 0; mf < 2; mf++)
                    ldsm4(a[mf], Pb + (uint32_t)(qb + mf * 16 + ar) * 272 + (k0 + ly) * 2);
#pragma unroll
                for (int cb = 0; cb < 4; cb++) {
                    uint32_t bb[4];
                    ldsm4t(bb, Vb + (uint32_t)(k0 + lx) * 528 + (cg * 64 + cb * 16 + ly) * 2);
                    mma16(oacc[0][cb * 2],     a[0], bb[0], bb[1]);
                    mma16(oacc[0][cb * 2 + 1], a[0], bb[2], bb[3]);
                    mma16(oacc[1][cb * 2],     a[1], bb[0], bb[1]);
                    mma16(oacc[1][cb * 2 + 1], a[1], bb[2], bb[3]);
                }
            }
        }
        __syncthreads();   // all reads of Ps done before Ostage overlays it

        // epilogue: two 128-channel passes through Ostage, coalesced writes
#pragma unroll
        for (int p = 0; p < 2; p++) {
            if ((cg >> 1) == p) {
#pragma unroll
                for (int mf = 0; mf < 2; mf++) {
                    float li0 = Linv[qb + mf * 16 + r0];
                    float li1 = Linv[qb + mf * 16 + 8 + r0];
#pragma unroll
                    for (int nf = 0; nf < 8; nf++) {
                        int c  = (cg & 1) * 64 + nf * 8 + 2 * c2;
                        int q0 = qb + mf * 16 + r0;
                        Ostage[(c    ) * 132 + q0    ] = oacc[mf][nf][0] * li0;
                        Ostage[(c + 1) * 132 + q0    ] = oacc[mf][nf][1] * li0;
                        Ostage[(c    ) * 132 + q0 + 8] = oacc[mf][nf][2] * li1;
                        Ostage[(c + 1) * 132 + q0 + 8] = oacc[mf][nf][3] * li1;
                    }
                }
            }
            __syncthreads();
#pragma unroll
            for (int j = 0; j < 8; j++) {
                int idx = j * 512 + t;
                int c = idx >> 5, q4 = idx & 31;
                float4 o = *(float4*)&Ostage[c * 132 + q4 * 4];
                size_t gidx = ((size_t)(b * NC + ch0 + p * 128 + c)) * NN + n0 + q4 * 4;
                float4 xv = *(const float4*)(x + gidx);
                float4 rr;
                rr.x = gv2 * o.x + xv.x;
                rr.y = gv2 * o.y + xv.y;
                rr.z = gv2 * o.z + xv.z;
                rr.w = gv2 * o.w + xv.w;
                *(float4*)(out + gidx) = rr;
            }
            __syncthreads();
        }
    }
}

// =========================================================================
extern "C" void kernel_launch(void* const* d_in, const int* in_sizes, int n_in,
                              void* d_out, int out_size)
{
    (void)in_sizes; (void)n_in; (void)out_size;
    const float* x     = (const float*)d_in[0];
    const float* wq    = (const float*)d_in[1];
    const float* bq    = (const float*)d_in[2];
    const float* wk    = (const float*)d_in[3];
    const float* bk    = (const float*)d_in[4];
    const float* wv    = (const float*)d_in[5];
    const float* bv    = (const float*)d_in[6];
    const float* gamma = (const float*)d_in[7];
    float* out = (float*)d_out;

    cudaFuncSetAttribute(pam_proj, cudaFuncAttributeMaxDynamicSharedMemorySize, SMEM_PJ);
    cudaFuncSetAttribute(pam_sp,   cudaFuncAttributeMaxDynamicSharedMemorySize, SMEM_SP);
    cudaFuncSetAttribute(pam_pv,   cudaFuncAttributeMaxDynamicSharedMemorySize, SMEM_PV);

    pam_roundw<<<320, 256>>>(wq, wk, wv);
    pam_proj<<<dim3(NN / 128, 640 / 128, NB), 256, SMEM_PJ>>>(x, bq, bk, bv);
    pam_sp<<<dim3(NN / 128, NB), 512, SMEM_SP>>>();
    pam_pv<<<dim3(NN / 128, 1, NB), 512, SMEM_PV>>>(x, gamma, out);
}

// round 17
// speedup vs baseline: 1.6900x; 1.0837x over previous
#include <cuda_runtime.h>
#include <cuda_bf16.h>
#include <cuda_fp16.h>
#include <cstdint>

#define NB  4
#define NC  512
#define NN  4096
#define NCQ 64

// ---------------- device scratch ----------------
__device__ float g_Wr[640 * NC];                     // rounded unified [wq;wk;wv]
__device__ __half g_Qh[NB * NN * NCQ];               // [b][n][k] fp16
__device__ __half g_Kh[NB * NN * NCQ];               // [b][m][k] fp16
__device__ __nv_bfloat16 g_Vh[(size_t)NB * NN * NC]; // [b][m][c] bf16
__device__ __nv_bfloat16 g_P[(size_t)NB * NN * NN];  // [b][q][m] bf16, 134 MB
__device__ float g_L[NB * NN];                       // 1 / sum(exp(s-20))

__device__ __forceinline__ float f2tff(float v) {
    uint32_t t;
    asm("cvt.rna.tf32.f32 %0, %1;" : "=r"(t) : "f"(v));
    return __uint_as_float(t);
}
__device__ __forceinline__ uint32_t f2tffu(float v) {
    uint32_t t;
    asm("cvt.rna.tf32.f32 %0, %1;" : "=r"(t) : "f"(v));
    return t;
}

__device__ __forceinline__ void mma8(float c[4],
                                     uint32_t a0, uint32_t a1, uint32_t a2, uint32_t a3,
                                     uint32_t b0, uint32_t b1) {
    asm volatile(
        "mma.sync.aligned.m16n8k8.row.col.f32.tf32.tf32.f32 "
        "{%0,%1,%2,%3},{%4,%5,%6,%7},{%8,%9},{%0,%1,%2,%3};"
        : "+f"(c[0]), "+f"(c[1]), "+f"(c[2]), "+f"(c[3])
        : "r"(a0), "r"(a1), "r"(a2), "r"(a3), "r"(b0), "r"(b1));
}

__device__ __forceinline__ void mma16(float c[4], const uint32_t a[4],
                                      uint32_t b0, uint32_t b1) {
    asm volatile(
        "mma.sync.aligned.m16n8k16.row.col.f32.bf16.bf16.f32 "
        "{%0,%1,%2,%3},{%4,%5,%6,%7},{%8,%9},{%0,%1,%2,%3};"
        : "+f"(c[0]), "+f"(c[1]), "+f"(c[2]), "+f"(c[3])
        : "r"(a[0]), "r"(a[1]), "r"(a[2]), "r"(a[3]), "r"(b0), "r"(b1));
}

__device__ __forceinline__ void mma16h(float c[4], const uint32_t a[4],
                                       uint32_t b0, uint32_t b1) {
    asm volatile(
        "mma.sync.aligned.m16n8k16.row.col.f32.f16.f16.f32 "
        "{%0,%1,%2,%3},{%4,%5,%6,%7},{%8,%9},{%0,%1,%2,%3};"
        : "+f"(c[0]), "+f"(c[1]), "+f"(c[2]), "+f"(c[3])
        : "r"(a[0]), "r"(a[1]), "r"(a[2]), "r"(a[3]), "r"(b0), "r"(b1));
}

__device__ __forceinline__ void ldsm4(uint32_t r[4], uint32_t addr) {
    asm volatile("ldmatrix.sync.aligned.m8n8.x4.shared.b16 {%0,%1,%2,%3},[%4];"
                 : "=r"(r[0]), "=r"(r[1]), "=r"(r[2]), "=r"(r[3]) : "r"(addr));
}
__device__ __forceinline__ void ldsm4t(uint32_t r[4], uint32_t addr) {
    asm volatile("ldmatrix.sync.aligned.m8n8.x4.trans.shared.b16 {%0,%1,%2,%3},[%4];"
                 : "=r"(r[0]), "=r"(r[1]), "=r"(r[2]), "=r"(r[3]) : "r"(addr));
}
__device__ __forceinline__ void cpa16(uint32_t s, const void* g) {
    asm volatile("cp.async.cg.shared.global [%0],[%1],16;" :: "r"(s), "l"(g));
}

// =========================================================================
// Kernel 0: pre-round W (once) into unified g_Wr[o][c], o in [0,640).
// =========================================================================
__global__ __launch_bounds__(256) void pam_roundw(
    const float* __restrict__ wq, const float* __restrict__ wk,
    const float* __restrict__ wv)
{
    int i = blockIdx.x * 256 + threadIdx.x;      // float4 index, 81920 total
    int p = i * 4;
    int o = p >> 9, c = p & 511;
    const float* src = (o < 64) ? (wq + (size_t)o * NC + c)
                     : (o < 128) ? (wk + (size_t)(o - 64) * NC + c)
                                 : (wv + (size_t)(o - 128) * NC + c);
    float4 v = *reinterpret_cast<const float4*>(src);
    v.x = f2tff(v.x); v.y = f2tff(v.y); v.z = f2tff(v.z); v.w = f2tff(v.w);
    *reinterpret_cast<float4*>(g_Wr + p) = v;
}

// =========================================================================
// Kernel 1: fused QKV projection (round-11 structure; Q/K now stored fp16).
// =========================================================================
#define PJ_WS    33792
#define SMEM_PJ  70656

__global__ __launch_bounds__(256) void pam_proj(
    const float* __restrict__ x,
    const float* __restrict__ bq, const float* __restrict__ bk,
    const float* __restrict__ bv)
{
    extern __shared__ char sm[];
    uint32_t sb = (uint32_t)__cvta_generic_to_shared(sm);
    const uint32_t AsA = sb, WsA = sb + PJ_WS;

    const int b  = blockIdx.z;
    const int n0 = blockIdx.x * 128;
    const int oc = blockIdx.y * 128;
    const int t    = threadIdx.x;
    const int lane = t & 31;
    const int wid  = t >> 5;
    const int mg = wid & 3, og = wid >> 2;
    const int m0 = mg * 32, o0 = og * 64;
    const int r0 = lane >> 2, c2 = lane & 3;

    const int wr  = ((lane >> 4) & 1) * 8 + (lane & 7);
    const int wk2 = ((lane >> 3) & 1) * 4;

    {
#pragma unroll
        for (int r = 0; r < 4; r++) {
            int idx = t + 256 * r;
            int kk = idx >> 5, j4 = idx & 31;
            cpa16(AsA + kk * 528 + j4 * 16,
                  x + ((size_t)(b * NC + kk)) * NN + n0 + j4 * 4);
        }
#pragma unroll
        for (int r = 0; r < 4; r++) {
            int idx = t + 256 * r;
            int row = idx >> 3, f4 = idx & 7;
            cpa16(WsA + row * 144 + f4 * 16,
                  g_Wr + (size_t)(oc + row) * NC + f4 * 4);
        }
        asm volatile("cp.async.commit_group;" ::: "memory");
    }

    float acc[2][8][4];
#pragma unroll
    for (int mf = 0; mf < 2; mf++)
#pragma unroll
        for (int nf = 0; nf < 8; nf++)
#pragma unroll
            for (int e = 0; e < 4; e++) acc[mf][nf][e] = 0.f;

    for (int it = 0; it < 16; it++) {
        const int buf = it & 1;
        if (it < 15) {
            const int nb = (it + 1) & 1, kc = (it + 1) * 32;
#pragma unroll
            for (int r = 0; r < 4; r++) {
                int idx = t + 256 * r;
                int kk = idx >> 5, j4 = idx & 31;
                cpa16(AsA + nb * 16896 + kk * 528 + j4 * 16,
                      x + ((size_t)(b * NC + kc + kk)) * NN + n0 + j4 * 4);
            }
#pragma unroll
            for (int r = 0; r < 4; r++) {
                int idx = t + 256 * r;
                int row = idx >> 3, f4 = idx & 7;
                cpa16(WsA + nb * 18432 + row * 144 + f4 * 16,
                      g_Wr + (size_t)(oc + row) * NC + kc + f4 * 4);
            }
            asm volatile("cp.async.commit_group;" ::: "memory");
            asm volatile("cp.async.wait_group 1;" ::: "memory");
        } else {
            asm volatile("cp.async.wait_group 0;" ::: "memory");
        }
        __syncthreads();

        const float* AsB = (const float*)(sm + buf * 16896);
        const uint32_t WsB = WsA + buf * 18432;

#pragma unroll
        for (int kq = 0; kq < 32; kq += 8) {
            uint32_t a[2][4];
#pragma unroll
            for (int mf = 0; mf < 2; mf++) {
                const float* Ab = AsB + (kq + c2) * 132 + m0 + mf * 16 + r0;
                a[mf][0] = f2tffu(Ab[0]);
                a[mf][1] = f2tffu(Ab[8]);
                a[mf][2] = f2tffu(Ab[4 * 132]);
                a[mf][3] = f2tffu(Ab[4 * 132 + 8]);
            }
#pragma unroll
            for (int i = 0; i < 4; i++) {
                uint32_t wf[4];
                ldsm4(wf, WsB + (uint32_t)(o0 + i * 16 + wr) * 144 + (kq + wk2) * 4);
                mma8(acc[0][2 * i],     a[0][0], a[0][1], a[0][2], a[0][3], wf[0], wf[1]);
                mma8(acc[0][2 * i + 1], a[0][0], a[0][1], a[0][2], a[0][3], wf[2], wf[3]);
                mma8(acc[1][2 * i],     a[1][0], a[1][1], a[1][2], a[1][3], wf[0], wf[1]);
                mma8(acc[1][2 * i + 1], a[1][0], a[1][1], a[1][2], a[1][3], wf[2], wf[3]);
            }
        }
        __syncthreads();
    }

    const int c0 = 2 * (lane & 3);
#pragma unroll
    for (int mf = 0; mf < 2; mf++) {
#pragma unroll
        for (int nf = 0; nf < 8; nf++) {
#pragma unroll
            for (int e = 0; e < 4; e++) {
                int row = m0 + mf * 16 + r0 + ((e >= 2) ? 8 : 0);
                int col = o0 + (nf >> 1) * 16 + (nf & 1) * 8 + c0 + (e & 1);
                int o = oc + col;
                int n = n0 + row;
                if (o < 64) {
                    g_Qh[((size_t)b * NN + n) * NCQ + o] = __float2half(acc[mf][nf][e] + bq[o]);
                } else if (o < 128) {
                    g_Kh[((size_t)b * NN + n) * NCQ + (o - 64)] = __float2half(acc[mf][nf][e] + bk[o - 64]);
                } else {
                    g_Vh[((size_t)b * NN + n) * NC + (o - 128)] =
                        __float2bfloat16(acc[mf][nf][e] + bv[o - 128]);
                }
            }
        }
    }
}

// =========================================================================
// Kernel 2: S = Q K^T in FP16 (m16n8k16, 2x tf32 rate), P = exp(S-20) ->
// global bf16 via smem staging, Linv -> global. Grid 32 x 4 = 128 CTAs.
// Smem: Qs f16[128][72] | Ks f16[2][64][72] | Lpart | Pstage bf16[128][72]
// =========================================================================
#define SP_KS    18432
#define SP_LP    36864
#define SP_PST   38912
#define SMEM_SP  57344

__global__ __launch_bounds__(512, 1) void pam_sp()
{
    extern __shared__ char sm[];
    float* Lpart = (float*)(sm + SP_LP);
    __nv_bfloat16* Pst = (__nv_bfloat16*)(sm + SP_PST);
    uint32_t sb = (uint32_t)__cvta_generic_to_shared(sm);
    const uint32_t QsA = sb, KsA = sb + SP_KS;

    const int b  = blockIdx.y;
    const int n0 = blockIdx.x * 128;
    const int t = threadIdx.x, lane = t & 31, wid = t >> 5;
    const int qs = wid >> 2, mg = wid & 3;
    const int qb = qs * 32;
    const int r0 = lane >> 2, c2 = lane & 3;

    // f16 m16n8k16 ldsm selectors (proven in pv's P path)
    const int ar = (lane & 7) + ((lane >> 3) & 1) * 8;
    const int ly = (lane >> 4) * 8;

    {
        const __half* gq = g_Qh + ((size_t)b * NN + n0) * NCQ;
#pragma unroll
        for (int r2 = 0; r2 < 2; r2++) {
            int cid = t + 512 * r2; int row = cid >> 3, ch = cid & 7;
            cpa16(QsA + row * 144 + ch * 16, gq + row * 64 + ch * 8);
        }
        const __half* gk = g_Kh + ((size_t)b * NN) * NCQ;
        {
            int row = t >> 3, ch = t & 7;
            cpa16(KsA + row * 144 + ch * 16, gk + row * 64 + ch * 8);
        }
        asm volatile("cp.async.commit_group;" ::: "memory");
    }

    float Lacc[4] = {0.f, 0.f, 0.f, 0.f};
    __nv_bfloat16* gp = g_P + ((size_t)b * NN + n0) * NN;

    for (int mt = 0; mt < 64; mt++) {
        const int buf = mt & 1;
        if (mt < 63) {
            const int nb = (mt + 1) & 1;
            const __half* gk = g_Kh + ((size_t)b * NN + (mt + 1) * 64) * NCQ;
            {
                int row = t >> 3, ch = t & 7;
                cpa16(KsA + nb * 9216 + row * 144 + ch * 16, gk + row * 64 + ch * 8);
            }
            asm volatile("cp.async.commit_group;" ::: "memory");
            asm volatile("cp.async.wait_group 1;" ::: "memory");
        } else {
            asm volatile("cp.async.wait_group 0;" ::: "memory");
        }
        __syncthreads();

        // S = Q K^T (fp16), warp: 32q x 16m, 4 k16 steps
        const uint32_t KbA = KsA + buf * 9216;
        float sacc[2][2][4];
#pragma unroll
        for (int mf = 0; mf < 2; mf++)
#pragma unroll
            for (int nf = 0; nf < 2; nf++)
#pragma unroll
                for (int e = 0; e < 4; e++) sacc[mf][nf][e] = 0.f;

#pragma unroll
        for (int ks = 0; ks < 4; ks++) {
            uint32_t kf[4];
            // r0=(m0-7,klo) r1=(m8-15,klo) r2=(m0-7,khi) r3=(m8-15,khi)
            ldsm4(kf, KbA + (uint32_t)(mg * 16 + ar) * 144 + (ks * 16 + ly) * 2);
#pragma unroll
            for (int mf = 0; mf < 2; mf++) {
                uint32_t qf[4];
                ldsm4(qf, QsA + (uint32_t)(qb + mf * 16 + ar) * 144 + (ks * 16 + ly) * 2);
                mma16h(sacc[mf][0], qf, kf[0], kf[2]);
                mma16h(sacc[mf][1], qf, kf[1], kf[3]);
            }
        }

        // P = exp(S - 20) -> smem stage (bf16), accumulate L
#pragma unroll
        for (int mf = 0; mf < 2; mf++)
#pragma unroll
            for (int nf = 0; nf < 2; nf++)
#pragma unroll
                for (int h = 0; h < 2; h++) {
                    float e0 = __expf(sacc[mf][nf][2 * h]     - 20.f);
                    float e1 = __expf(sacc[mf][nf][2 * h + 1] - 20.f);
                    Lacc[mf * 2 + h] += e0 + e1;
                    uint32_t pk;
                    asm("cvt.rn.bf16x2.f32 %0, %1, %2;" : "=r"(pk) : "f"(e1), "f"(e0));
                    int q = qb + mf * 16 + h * 8 + r0;
                    int m = mg * 16 + nf * 8 + 2 * c2;
                    *(uint32_t*)((char*)Pst + q * 144 + m * 2) = pk;
                }
        __syncthreads();

        // coalesced 16B stores: 128 rows x 128B
#pragma unroll
        for (int r2 = 0; r2 < 2; r2++) {
            int idx = t + 512 * r2;
            int row = idx >> 3, ch = idx & 7;
            *(float4*)(gp + (size_t)row * NN + mt * 64 + ch * 8) =
                *(const float4*)((const char*)Pst + row * 144 + ch * 16);
        }
    }

    // deterministic L reduction -> g_L holds the INVERSE
#pragma unroll
    for (int i = 0; i < 4; i++) {
        float v = Lacc[i];
        v += __shfl_xor_sync(0xffffffffu, v, 1);
        v += __shfl_xor_sync(0xffffffffu, v, 2);
        if (c2 == 0) Lpart[mg * 128 + qb + (i >> 1) * 16 + (i & 1) * 8 + r0] = v;
    }
    __syncthreads();
    if (t < 128)
        g_L[(size_t)b * NN + n0 + t] =
            1.f / (Lpart[t] + Lpart[128 + t] + Lpart[256 + t] + Lpart[384 + t]);
}

// =========================================================================
// Kernel 3: O = P @ V + epilogue (round-16 passing version: 512 thr, 128q,
// 128-key tiles, 32 sync pairs, persistent over 2 channel halves).
// Smem: Ps bf16[2][128][136] | Vs bf16[2][128][264] | Linv f32[128]
// =========================================================================
#define PV_VS    69632
#define PV_LI    204800
#define SMEM_PV  205312

__global__ __launch_bounds__(512, 1) void pam_pv(
    const float* __restrict__ x,
    const float* __restrict__ gamma,
    float* __restrict__ out)
{
    extern __shared__ char sm[];
    float* Linv   = (float*)(sm + PV_LI);
    float* Ostage = (float*)sm;
    uint32_t sb = (uint32_t)__cvta_generic_to_shared(sm);
    const uint32_t PsA = sb, VsA = sb + PV_VS;

    const int b   = blockIdx.z;
    const int n0  = blockIdx.x * 128;
    const int t = threadIdx.x, lane = t & 31, wid = t >> 5;
    const int qs = wid >> 2, cg = wid & 3;
    const int qb = qs * 32;
    const int r0 = lane >> 2, c2 = lane & 3;

    const __nv_bfloat16* __restrict__ gp = g_P + ((size_t)b * NN + n0) * NN;

    if (t < 128) Linv[t] = g_L[(size_t)b * NN + n0 + t];

    const int ar = (lane & 7) + ((lane >> 3) & 1) * 8;
    const int ly = (lane >> 4) * 8;
    const int lx = lane & 15;
    const float gv2 = gamma[0];

    for (int p2 = 0; p2 < 2; p2++) {
        const int ch0 = p2 * 256;
        const __nv_bfloat16* gv = g_Vh + ((size_t)b * NN) * NC + ch0;

        // prologue: tile 0 (P 128x128, V 128x256), one commit group
        {
#pragma unroll
            for (int r2 = 0; r2 < 4; r2++) {
                int cid = t + 512 * r2; int row = cid >> 4, ch = cid & 15;
                cpa16(PsA + row * 272 + ch * 16, gp + (size_t)row * NN + ch * 8);
            }
#pragma unroll
            for (int r2 = 0; r2 < 8; r2++) {
                int cid = t + 512 * r2; int row = cid >> 5, c16 = cid & 31;
                cpa16(VsA + row * 528 + c16 * 16, gv + (size_t)row * NC + c16 * 8);
            }
            asm volatile("cp.async.commit_group;" ::: "memory");
        }

        float oacc[2][8][4];
#pragma unroll
        for (int mf = 0; mf < 2; mf++)
#pragma unroll
            for (int nf = 0; nf < 8; nf++)
#pragma unroll
                for (int e = 0; e < 4; e++) oacc[mf][nf][e] = 0.f;

        for (int mt = 0; mt < 32; mt++) {
            asm volatile("cp.async.wait_group 0;" ::: "memory");
            __syncthreads();   // tile mt visible; all warps done with other slot

            // prefetch tile mt+1 into other slot (overlaps with compute of mt)
            if (mt < 31) {
                const int sl = (mt + 1) & 1, m1 = (mt + 1) * 128;
#pragma unroll
                for (int r2 = 0; r2 < 4; r2++) {
                    int cid = t + 512 * r2; int row = cid >> 4, ch = cid & 15;
                    cpa16(PsA + sl * 34816 + row * 272 + ch * 16,
                          gp + (size_t)row * NN + m1 + ch * 8);
                }
#pragma unroll
                for (int r2 = 0; r2 < 8; r2++) {
                    int cid = t + 512 * r2; int row = cid >> 5, c16 = cid & 31;
                    cpa16(VsA + sl * 67584 + row * 528 + c16 * 16,
                          gv + (size_t)(m1 + row) * NC + c16 * 8);
                }
                asm volatile("cp.async.commit_group;" ::: "memory");
            }

            const uint32_t Pb = PsA + (mt & 1) * 34816;
            const uint32_t Vb = VsA + (mt & 1) * 67584;
#pragma unroll
            for (int ks = 0; ks < 8; ks++) {
                const int k0 = ks * 16;
                uint32_t a[2][4];
#pragma unroll
                for (int mf = 0; mf < 2; mf++)
                    ldsm4(a[mf], Pb + (uint32_t)(qb + mf * 16 + ar) * 272 + (k0 + ly) * 2);
#pragma unroll
                for (int cb = 0; cb < 4; cb++) {
                    uint32_t bb[4];
                    ldsm4t(bb, Vb + (uint32_t)(k0 + lx) * 528 + (cg * 64 + cb * 16 + ly) * 2);
                    mma16(oacc[0][cb * 2],     a[0], bb[0], bb[1]);
                    mma16(oacc[0][cb * 2 + 1], a[0], bb[2], bb[3]);
                    mma16(oacc[1][cb * 2],     a[1], bb[0], bb[1]);
                    mma16(oacc[1][cb * 2 + 1], a[1], bb[2], bb[3]);
                }
            }
        }
        __syncthreads();   // all reads of Ps done before Ostage overlays it

        // epilogue: two 128-channel passes through Ostage, coalesced writes
#pragma unroll
        for (int p = 0; p < 2; p++) {
            if ((cg >> 1) == p) {
#pragma unroll
                for (int mf = 0; mf < 2; mf++) {
                    float li0 = Linv[qb + mf * 16 + r0];
                    float li1 = Linv[qb + mf * 16 + 8 + r0];
#pragma unroll
                    for (int nf = 0; nf < 8; nf++) {
                        int c  = (cg & 1) * 64 + nf * 8 + 2 * c2;
                        int q0 = qb + mf * 16 + r0;
                        Ostage[(c    ) * 132 + q0    ] = oacc[mf][nf][0] * li0;
                        Ostage[(c + 1) * 132 + q0    ] = oacc[mf][nf][1] * li0;
                        Ostage[(c    ) * 132 + q0 + 8] = oacc[mf][nf][2] * li1;
                        Ostage[(c + 1) * 132 + q0 + 8] = oacc[mf][nf][3] * li1;
                    }
                }
            }
            __syncthreads();
#pragma unroll
            for (int j = 0; j < 8; j++) {
                int idx = j * 512 + t;
                int c = idx >> 5, q4 = idx & 31;
                float4 o = *(float4*)&Ostage[c * 132 + q4 * 4];
                size_t gidx = ((size_t)(b * NC + ch0 + p * 128 + c)) * NN + n0 + q4 * 4;
                float4 xv = *(const float4*)(x + gidx);
                float4 rr;
                rr.x = gv2 * o.x + xv.x;
                rr.y = gv2 * o.y + xv.y;
                rr.z = gv2 * o.z + xv.z;
                rr.w = gv2 * o.w + xv.w;
                *(float4*)(out + gidx) = rr;
            }
            __syncthreads();
        }
    }
}

// =========================================================================
extern "C" void kernel_launch(void* const* d_in, const int* in_sizes, int n_in,
                              void* d_out, int out_size)
{
    (void)in_sizes; (void)n_in; (void)out_size;
    const float* x     = (const float*)d_in[0];
    const float* wq    = (const float*)d_in[1];
    const float* bq    = (const float*)d_in[2];
    const float* wk    = (const float*)d_in[3];
    const float* bk    = (const float*)d_in[4];
    const float* wv    = (const float*)d_in[5];
    const float* bv    = (const float*)d_in[6];
    const float* gamma = (const float*)d_in[7];
    float* out = (float*)d_out;

    cudaFuncSetAttribute(pam_proj, cudaFuncAttributeMaxDynamicSharedMemorySize, SMEM_PJ);
    cudaFuncSetAttribute(pam_sp,   cudaFuncAttributeMaxDynamicSharedMemorySize, SMEM_SP);
    cudaFuncSetAttribute(pam_pv,   cudaFuncAttributeMaxDynamicSharedMemorySize, SMEM_PV);

    pam_roundw<<<320, 256>>>(wq, wk, wv);
    pam_proj<<<dim3(NN / 128, 640 / 128, NB), 256, SMEM_PJ>>>(x, bq, bk, bv);
    pam_sp<<<dim3(NN / 128, NB), 512, SMEM_SP>>>();
    pam_pv<<<dim3(NN / 128, 1, NB), 512, SMEM_PV>>>(x, gamma, out);
}